// round 15
// baseline (speedup 1.0000x reference)
#include <cuda_runtime.h>
#include <cuda_fp16.h>

#define NN 100000
#define EE 3200000

// ---------------- persistent device scratch ----------------
__device__ int            g_deg[NN];
__device__ unsigned short g_rank16[EE];   // per-edge rank within destination
__device__ int            g_rowstart[NN + 1];
__device__ int            g_bsum[512];
__device__ int            g_csr[EE];
__device__ float          g_dis[NN];
__device__ uint2          g_hA16[NN * 4]; // h~ fp16: 16 halves = 32 B/node
__device__ uint2          g_hB16[NN * 4];
__device__ float2         g_h3[NN];       // layer-3 h~ (2 f32/node)

// ---------------- fork/join resources (created once at load; no device mem) ----
static cudaStream_t g_s2;
static cudaEvent_t  g_evFork, g_evJoin;
static struct _StreamInit {
    _StreamInit() {
        cudaStreamCreateWithFlags(&g_s2, cudaStreamNonBlocking);
        cudaEventCreateWithFlags(&g_evFork, cudaEventDisableTiming);
        cudaEventCreateWithFlags(&g_evJoin, cudaEventDisableTiming);
    }
} g_streamInit;

// ---------------- fp16 pack/unpack ----------------
__device__ __forceinline__ unsigned pack2(float a, float b) {
    __half2 h = __floats2half2_rn(a, b);
    return *reinterpret_cast<unsigned*>(&h);
}
__device__ __forceinline__ float2 unpack2(unsigned u) {
    __half2 h = *reinterpret_cast<__half2*>(&u);
    return __half22float2(h);
}

// ---------------- CSR build ----------------
__global__ void count_rank(const int* __restrict__ ei, int e) {
    int i = blockIdx.x * 256 + threadIdx.x;
    if (i >= e) return;
    g_rank16[i] = (unsigned short)atomicAdd(&g_deg[ei[e + i]], 1);
}

__global__ void scanA(int n) {
    __shared__ int sh[256];
    int tid = threadIdx.x;
    int i = blockIdx.x * 256 + tid;
    int v = (i < n) ? g_deg[i] : 0;
    sh[tid] = v;
    __syncthreads();
    for (int off = 1; off < 256; off <<= 1) {
        int t = (tid >= off) ? sh[tid - off] : 0;
        __syncthreads();
        sh[tid] += t;
        __syncthreads();
    }
    if (i < n) g_rowstart[i] = sh[tid] - v;
    if (tid == 255) g_bsum[blockIdx.x] = sh[255];
}

__global__ void scanB(int n) {
    __shared__ int red[256];
    int tid = threadIdx.x, b = blockIdx.x;
    int s = 0;
    for (int j = tid; j < b; j += 256) s += g_bsum[j];
    red[tid] = s;
    __syncthreads();
    for (int st = 128; st; st >>= 1) {
        if (tid < st) red[tid] += red[tid + st];
        __syncthreads();
    }
    int off = red[0];
    int i = b * 256 + tid;
    if (i < n) {
        int rs = g_rowstart[i] + off;
        g_rowstart[i] = rs;
        int v = g_deg[i];
        g_dis[i] = rsqrtf((float)(v + 1));
        if (i == n - 1) g_rowstart[n] = rs + v;
    }
}

__global__ void fill_pos(const int* __restrict__ ei, int e) {
    int i = blockIdx.x * 256 + threadIdx.x;
    if (i >= e) return;
    int s = ei[i];
    int d = ei[e + i];
    g_csr[g_rowstart[d] + (int)g_rank16[i]] = s;
}

// ---------------- layer 1: h = x @ W1 -> fp16 (UNSCALED; fork branch) ----------------
__global__ void gemm_in(const float4* __restrict__ x4, const float4* __restrict__ W1v, int n) {
    __shared__ float4 wt[512];          // W1 [128][16] as float4 (8 KB)
    __shared__ float4 xs[256 * 9];      // 256 node rows, padded (36 KB)

    int tid = threadIdx.x;
    for (int idx = tid; idx < 512; idx += 256) wt[idx] = W1v[idx];

    int nb = blockIdx.x * 256;
    int myNode = nb + tid;
    int f = tid & 7;
    int ndBase = tid >> 3;

    float acc[16];
#pragma unroll
    for (int j = 0; j < 16; j++) acc[j] = 0.f;

    for (int c = 0; c < 4; c++) {
        __syncthreads();
#pragma unroll
        for (int i = 0; i < 8; i++) {
            int nd = ndBase + i * 32;
            int node = nb + nd;
            float4 v = (node < n) ? __ldg(&x4[(size_t)node * 32 + c * 8 + f])
                                  : make_float4(0.f, 0.f, 0.f, 0.f);
            xs[nd * 9 + f] = v;
        }
        __syncthreads();
#pragma unroll
        for (int i = 0; i < 8; i++) {
            float4 v = xs[tid * 9 + i];
            int kb = (c * 8 + i) * 16;
#pragma unroll
            for (int j = 0; j < 4; j++) {
                float xs_ = (j == 0) ? v.x : (j == 1) ? v.y : (j == 2) ? v.z : v.w;
                float4 w0 = wt[kb + j * 4 + 0];
                float4 w1 = wt[kb + j * 4 + 1];
                float4 w2 = wt[kb + j * 4 + 2];
                float4 w3 = wt[kb + j * 4 + 3];
                acc[0]  += xs_ * w0.x; acc[1]  += xs_ * w0.y; acc[2]  += xs_ * w0.z; acc[3]  += xs_ * w0.w;
                acc[4]  += xs_ * w1.x; acc[5]  += xs_ * w1.y; acc[6]  += xs_ * w1.z; acc[7]  += xs_ * w1.w;
                acc[8]  += xs_ * w2.x; acc[9]  += xs_ * w2.y; acc[10] += xs_ * w2.z; acc[11] += xs_ * w2.w;
                acc[12] += xs_ * w3.x; acc[13] += xs_ * w3.y; acc[14] += xs_ * w3.z; acc[15] += xs_ * w3.w;
            }
        }
    }

    if (myNode < n) {
#pragma unroll
        for (int q = 0; q < 4; q++)
            g_hA16[myNode * 4 + q] = make_uint2(pack2(acc[q*4+0], acc[q*4+1]),
                                                pack2(acc[q*4+2], acc[q*4+3]));
    }
}

// ---------------- after join: scale hA in place by dis ----------------
__global__ void scale_hA(int n) {
    int i = blockIdx.x * 256 + threadIdx.x;   // one node-quad per thread
    if (i >= n * 4) return;
    float d = g_dis[i >> 2];
    uint2 v = g_hA16[i];
    float2 a = unpack2(v.x), b = unpack2(v.y);
    g_hA16[i] = make_uint2(pack2(a.x * d, a.y * d), pack2(b.x * d, b.y * d));
}

// ---------------- fused gather + layer-2 transform ----------------
// One warp per node: gather h~A over in-edges; agg = dis*(sum+self);
// z = relu(agg + b1); h~B = (z @ W2) * dis -> fp16. All in-warp.
__global__ void gather_mid(const float* __restrict__ b1, const float4* __restrict__ W2, int n) {
    __shared__ float4 Ws[64];
    __shared__ float  bs[16];
    int tid = threadIdx.x;
    if (tid < 64) Ws[tid] = W2[tid];
    if (tid < 16) bs[tid] = b1[tid];
    __syncthreads();

    int w = (blockIdx.x * 256 + tid) >> 5;
    if (w >= n) return;
    int lane = tid & 31;
    int q = lane & 3, sub = lane >> 2;
    int start = g_rowstart[w], deg = g_rowstart[w + 1] - start;

    float4 acc = make_float4(0.f, 0.f, 0.f, 0.f);
    for (int base = 0; base < deg; base += 32) {
        int p = base + lane;
        int idx = (p < deg) ? __ldg(&g_csr[start + p]) : 0;
        int s0 = __shfl_sync(0xffffffffu, idx, sub);
        int s1 = __shfl_sync(0xffffffffu, idx, sub + 8);
        int s2 = __shfl_sync(0xffffffffu, idx, sub + 16);
        int s3 = __shfl_sync(0xffffffffu, idx, sub + 24);
        uint2 zz = make_uint2(0u, 0u);
        uint2 a = (base + sub)      < deg ? __ldg(&g_hA16[s0 * 4 + q]) : zz;
        uint2 b = (base + sub + 8)  < deg ? __ldg(&g_hA16[s1 * 4 + q]) : zz;
        uint2 c = (base + sub + 16) < deg ? __ldg(&g_hA16[s2 * 4 + q]) : zz;
        uint2 d = (base + sub + 24) < deg ? __ldg(&g_hA16[s3 * 4 + q]) : zz;
        float2 t;
        t = unpack2(a.x); acc.x += t.x; acc.y += t.y;
        t = unpack2(a.y); acc.z += t.x; acc.w += t.y;
        t = unpack2(b.x); acc.x += t.x; acc.y += t.y;
        t = unpack2(b.y); acc.z += t.x; acc.w += t.y;
        t = unpack2(c.x); acc.x += t.x; acc.y += t.y;
        t = unpack2(c.y); acc.z += t.x; acc.w += t.y;
        t = unpack2(d.x); acc.x += t.x; acc.y += t.y;
        t = unpack2(d.y); acc.z += t.x; acc.w += t.y;
    }
#pragma unroll
    for (int m = 4; m < 32; m <<= 1) {
        acc.x += __shfl_xor_sync(0xffffffffu, acc.x, m);
        acc.y += __shfl_xor_sync(0xffffffffu, acc.y, m);
        acc.z += __shfl_xor_sync(0xffffffffu, acc.z, m);
        acc.w += __shfl_xor_sync(0xffffffffu, acc.w, m);
    }
    // all lanes hold the full sum for their feature quad q
    uint2 hv = __ldg(&g_hA16[w * 4 + q]);   // self-loop
    float2 t0 = unpack2(hv.x), t1 = unpack2(hv.y);
    float d = g_dis[w];
    float4 z;
    z.x = fmaxf((acc.x + t0.x) * d + bs[q*4+0], 0.f);
    z.y = fmaxf((acc.y + t0.y) * d + bs[q*4+1], 0.f);
    z.z = fmaxf((acc.z + t1.x) * d + bs[q*4+2], 0.f);
    z.w = fmaxf((acc.w + t1.y) * d + bs[q*4+3], 0.f);

    // in-warp z @ W2 for output quad q
    float4 o = make_float4(0.f, 0.f, 0.f, 0.f);
#pragma unroll
    for (int j = 0; j < 4; j++) {
        int srcl = (lane & ~3) | j;
        float zx = __shfl_sync(0xffffffffu, z.x, srcl);
        float zy = __shfl_sync(0xffffffffu, z.y, srcl);
        float zz2 = __shfl_sync(0xffffffffu, z.z, srcl);
        float zw = __shfl_sync(0xffffffffu, z.w, srcl);
        float4 w0 = Ws[(j*4+0)*4 + q];
        float4 w1 = Ws[(j*4+1)*4 + q];
        float4 w2 = Ws[(j*4+2)*4 + q];
        float4 w3 = Ws[(j*4+3)*4 + q];
        o.x += zx*w0.x + zy*w1.x + zz2*w2.x + zw*w3.x;
        o.y += zx*w0.y + zy*w1.y + zz2*w2.y + zw*w3.y;
        o.z += zx*w0.z + zy*w1.z + zz2*w2.z + zw*w3.z;
        o.w += zx*w0.w + zy*w1.w + zz2*w2.w + zw*w3.w;
    }
    if (sub == 0)
        g_hB16[w * 4 + q] = make_uint2(pack2(o.x * d, o.y * d), pack2(o.z * d, o.w * d));
}

// ---------------- fused gather + layer-3 transform ----------------
__global__ void gather_last(const float* __restrict__ b2, const float* __restrict__ W3, int n) {
    __shared__ float2 Ws[16];
    __shared__ float  bs[16];
    int tid = threadIdx.x;
    if (tid < 16) {
        Ws[tid] = make_float2(W3[tid*2], W3[tid*2+1]);
        bs[tid] = b2[tid];
    }
    __syncthreads();

    int w = (blockIdx.x * 256 + tid) >> 5;
    if (w >= n) return;
    int lane = tid & 31;
    int q = lane & 3, sub = lane >> 2;
    int start = g_rowstart[w], deg = g_rowstart[w + 1] - start;

    float4 acc = make_float4(0.f, 0.f, 0.f, 0.f);
    for (int base = 0; base < deg; base += 32) {
        int p = base + lane;
        int idx = (p < deg) ? __ldg(&g_csr[start + p]) : 0;
        int s0 = __shfl_sync(0xffffffffu, idx, sub);
        int s1 = __shfl_sync(0xffffffffu, idx, sub + 8);
        int s2 = __shfl_sync(0xffffffffu, idx, sub + 16);
        int s3 = __shfl_sync(0xffffffffu, idx, sub + 24);
        uint2 zz = make_uint2(0u, 0u);
        uint2 a = (base + sub)      < deg ? __ldg(&g_hB16[s0 * 4 + q]) : zz;
        uint2 b = (base + sub + 8)  < deg ? __ldg(&g_hB16[s1 * 4 + q]) : zz;
        uint2 c = (base + sub + 16) < deg ? __ldg(&g_hB16[s2 * 4 + q]) : zz;
        uint2 d = (base + sub + 24) < deg ? __ldg(&g_hB16[s3 * 4 + q]) : zz;
        float2 t;
        t = unpack2(a.x); acc.x += t.x; acc.y += t.y;
        t = unpack2(a.y); acc.z += t.x; acc.w += t.y;
        t = unpack2(b.x); acc.x += t.x; acc.y += t.y;
        t = unpack2(b.y); acc.z += t.x; acc.w += t.y;
        t = unpack2(c.x); acc.x += t.x; acc.y += t.y;
        t = unpack2(c.y); acc.z += t.x; acc.w += t.y;
        t = unpack2(d.x); acc.x += t.x; acc.y += t.y;
        t = unpack2(d.y); acc.z += t.x; acc.w += t.y;
    }
#pragma unroll
    for (int m = 4; m < 32; m <<= 1) {
        acc.x += __shfl_xor_sync(0xffffffffu, acc.x, m);
        acc.y += __shfl_xor_sync(0xffffffffu, acc.y, m);
        acc.z += __shfl_xor_sync(0xffffffffu, acc.z, m);
        acc.w += __shfl_xor_sync(0xffffffffu, acc.w, m);
    }
    uint2 hv = __ldg(&g_hB16[w * 4 + q]);   // self-loop
    float2 t0 = unpack2(hv.x), t1 = unpack2(hv.y);
    float d = g_dis[w];
    float4 z;
    z.x = fmaxf((acc.x + t0.x) * d + bs[q*4+0], 0.f);
    z.y = fmaxf((acc.y + t0.y) * d + bs[q*4+1], 0.f);
    z.z = fmaxf((acc.z + t1.x) * d + bs[q*4+2], 0.f);
    z.w = fmaxf((acc.w + t1.y) * d + bs[q*4+3], 0.f);

    float o0 = 0.f, o1 = 0.f;
#pragma unroll
    for (int j = 0; j < 4; j++) {
        int srcl = (lane & ~3) | j;
        float zx = __shfl_sync(0xffffffffu, z.x, srcl);
        float zy = __shfl_sync(0xffffffffu, z.y, srcl);
        float zz2 = __shfl_sync(0xffffffffu, z.z, srcl);
        float zw = __shfl_sync(0xffffffffu, z.w, srcl);
        float2 w0 = Ws[j*4+0], w1 = Ws[j*4+1], w2 = Ws[j*4+2], w3 = Ws[j*4+3];
        o0 += zx*w0.x + zy*w1.x + zz2*w2.x + zw*w3.x;
        o1 += zx*w0.y + zy*w1.y + zz2*w2.y + zw*w3.y;
    }
    if (lane == 0) g_h3[w] = make_float2(o0 * d, o1 * d);
}

// ---------------- 2-wide gather fused with log_softmax ----------------
__global__ void gather2_out(const float* __restrict__ b3, float* __restrict__ out, int n) {
    int w = (blockIdx.x * 256 + threadIdx.x) >> 5;
    if (w >= n) return;
    int lane = threadIdx.x & 31;
    int start = g_rowstart[w], end = g_rowstart[w + 1];

    float2 acc = make_float2(0.f, 0.f);
    for (int p = start + lane; p < end; p += 32) {
        int src = __ldg(&g_csr[p]);
        float2 v = __ldg(&g_h3[src]);
        acc.x += v.x; acc.y += v.y;
    }
#pragma unroll
    for (int m = 1; m < 32; m <<= 1) {
        acc.x += __shfl_xor_sync(0xffffffffu, acc.x, m);
        acc.y += __shfl_xor_sync(0xffffffffu, acc.y, m);
    }
    if (lane == 0) {
        float2 hv = g_h3[w];
        float d = g_dis[w];
        float a0 = (acc.x + hv.x) * d + b3[0];
        float a1 = (acc.y + hv.y) * d + b3[1];
        float m0 = fmaxf(a0, a1);
        float lse = m0 + logf(expf(a0 - m0) + expf(a1 - m0));
        out[w * 2 + 0] = a0 - lse;
        out[w * 2 + 1] = a1 - lse;
    }
}

// ---------------- launch ----------------
extern "C" void kernel_launch(void* const* d_in, const int* in_sizes, int n_in,
                              void* d_out, int out_size) {
    const float* x  = (const float*)d_in[0];
    const int*   ei = (const int*)d_in[1];
    const float* W1 = (const float*)d_in[2];
    const float* b1 = (const float*)d_in[3];
    const float* W2 = (const float*)d_in[4];
    const float* b2 = (const float*)d_in[5];
    const float* W3 = (const float*)d_in[6];
    const float* b3 = (const float*)d_in[7];
    float* out = (float*)d_out;

    int n = in_sizes[0] / 128;   // 100000
    int e = in_sizes[1] / 2;     // 3200000

    int nb  = (n + 255) / 256;       // 391
    int ebk = (e + 255) / 256;       // 12500
    int wgb = (n * 32 + 255) / 256;  // warp-per-node grids
    int sb  = (n * 4 + 255) / 256;   // scale_hA grid

    void* degp = nullptr;
    cudaGetSymbolAddress(&degp, g_deg);

    // ---- fork: gemm_in (no dependencies) on g_s2, concurrent with CSR build ----
    cudaEventRecord(g_evFork, 0);
    cudaStreamWaitEvent(g_s2, g_evFork, 0);
    gemm_in<<<nb, 256, 0, g_s2>>>((const float4*)x, (const float4*)W1, n);
    cudaEventRecord(g_evJoin, g_s2);

    // ---- CSR build chain on main stream ----
    cudaMemsetAsync(degp, 0, (size_t)n * sizeof(int));
    count_rank<<<ebk, 256>>>(ei, e);
    scanA<<<nb, 256>>>(n);
    scanB<<<nb, 256>>>(n);
    fill_pos<<<ebk, 256>>>(ei, e);

    // ---- join, then scale hA by dis ----
    cudaStreamWaitEvent(0, g_evJoin, 0);
    scale_hA<<<sb, 256>>>(n);

    gather_mid<<<wgb, 256>>>(b1, (const float4*)W2, n);
    gather_last<<<wgb, 256>>>(b2, W3, n);
    gather2_out<<<wgb, 256>>>(b3, out, n);
}

// round 17
// speedup vs baseline: 1.2192x; 1.2192x over previous
#include <cuda_runtime.h>
#include <cuda_fp16.h>

#define NN 100000
#define EE 3200000

// ---------------- persistent device scratch ----------------
__device__ int            g_deg[NN];
__device__ unsigned short g_rank16[EE];   // per-edge rank within destination
__device__ int            g_rowstart[NN + 1];
__device__ int            g_bsum[512];
__device__ int            g_csr[EE];
__device__ float          g_dis[NN];
__device__ uint2          g_hA16[NN * 4]; // h fp16 (unscaled by gemm; scaled in scale_hA)
__device__ uint2          g_hB16[NN * 4];
__device__ float4         g_aggA[NN * 4]; // aggregates fp32 (linear access)
__device__ float4         g_aggB[NN * 4];
__device__ float2         g_h3[NN];       // layer-3 h~ (2 f32/node)

// ---------------- fork/join resources (host-side; no device mem) ----------------
static cudaStream_t g_s2;
static cudaEvent_t  g_evFork, g_evDis, g_evJoin;
static struct _StreamInit {
    _StreamInit() {
        cudaStreamCreateWithFlags(&g_s2, cudaStreamNonBlocking);
        cudaEventCreateWithFlags(&g_evFork, cudaEventDisableTiming);
        cudaEventCreateWithFlags(&g_evDis,  cudaEventDisableTiming);
        cudaEventCreateWithFlags(&g_evJoin, cudaEventDisableTiming);
    }
} g_streamInit;

// ---------------- fp16 pack/unpack ----------------
__device__ __forceinline__ unsigned pack2(float a, float b) {
    __half2 h = __floats2half2_rn(a, b);
    return *reinterpret_cast<unsigned*>(&h);
}
__device__ __forceinline__ float2 unpack2(unsigned u) {
    __half2 h = *reinterpret_cast<__half2*>(&u);
    return __half22float2(h);
}

// ---------------- CSR build ----------------
__global__ void count_rank(const int* __restrict__ ei, int e) {
    int i = blockIdx.x * 256 + threadIdx.x;
    if (i >= e) return;
    g_rank16[i] = (unsigned short)atomicAdd(&g_deg[ei[e + i]], 1);
}

__global__ void scanA(int n) {
    __shared__ int sh[256];
    int tid = threadIdx.x;
    int i = blockIdx.x * 256 + tid;
    int v = (i < n) ? g_deg[i] : 0;
    sh[tid] = v;
    __syncthreads();
    for (int off = 1; off < 256; off <<= 1) {
        int t = (tid >= off) ? sh[tid - off] : 0;
        __syncthreads();
        sh[tid] += t;
        __syncthreads();
    }
    if (i < n) g_rowstart[i] = sh[tid] - v;
    if (tid == 255) g_bsum[blockIdx.x] = sh[255];
}

__global__ void scanB(int n) {
    __shared__ int red[256];
    int tid = threadIdx.x, b = blockIdx.x;
    int s = 0;
    for (int j = tid; j < b; j += 256) s += g_bsum[j];
    red[tid] = s;
    __syncthreads();
    for (int st = 128; st; st >>= 1) {
        if (tid < st) red[tid] += red[tid + st];
        __syncthreads();
    }
    int off = red[0];
    int i = b * 256 + tid;
    if (i < n) {
        int rs = g_rowstart[i] + off;
        g_rowstart[i] = rs;
        int v = g_deg[i];
        g_dis[i] = rsqrtf((float)(v + 1));
        if (i == n - 1) g_rowstart[n] = rs + v;
    }
}

__global__ void fill_pos(const int* __restrict__ ei, int e) {
    int i = blockIdx.x * 256 + threadIdx.x;
    if (i >= e) return;
    int s = ei[i];
    int d = ei[e + i];
    g_csr[g_rowstart[d] + (int)g_rank16[i]] = s;
}

// ---------------- layer 1: h = x @ W1 -> fp16 (UNSCALED; fork branch) ----------------
__global__ void gemm_in(const float4* __restrict__ x4, const float4* __restrict__ W1v, int n) {
    __shared__ float4 wt[512];          // W1 [128][16] as float4
    __shared__ float4 xs[256 * 9];      // 256 node rows, padded

    int tid = threadIdx.x;
    for (int idx = tid; idx < 512; idx += 256) wt[idx] = W1v[idx];

    int nb = blockIdx.x * 256;
    int myNode = nb + tid;
    int f = tid & 7;
    int ndBase = tid >> 3;

    float acc[16];
#pragma unroll
    for (int j = 0; j < 16; j++) acc[j] = 0.f;

    for (int c = 0; c < 4; c++) {
        __syncthreads();
#pragma unroll
        for (int i = 0; i < 8; i++) {
            int nd = ndBase + i * 32;
            int node = nb + nd;
            float4 v = (node < n) ? __ldg(&x4[(size_t)node * 32 + c * 8 + f])
                                  : make_float4(0.f, 0.f, 0.f, 0.f);
            xs[nd * 9 + f] = v;
        }
        __syncthreads();
#pragma unroll
        for (int i = 0; i < 8; i++) {
            float4 v = xs[tid * 9 + i];
            int kb = (c * 8 + i) * 16;
#pragma unroll
            for (int j = 0; j < 4; j++) {
                float xs_ = (j == 0) ? v.x : (j == 1) ? v.y : (j == 2) ? v.z : v.w;
                float4 w0 = wt[kb + j * 4 + 0];
                float4 w1 = wt[kb + j * 4 + 1];
                float4 w2 = wt[kb + j * 4 + 2];
                float4 w3 = wt[kb + j * 4 + 3];
                acc[0]  += xs_ * w0.x; acc[1]  += xs_ * w0.y; acc[2]  += xs_ * w0.z; acc[3]  += xs_ * w0.w;
                acc[4]  += xs_ * w1.x; acc[5]  += xs_ * w1.y; acc[6]  += xs_ * w1.z; acc[7]  += xs_ * w1.w;
                acc[8]  += xs_ * w2.x; acc[9]  += xs_ * w2.y; acc[10] += xs_ * w2.z; acc[11] += xs_ * w2.w;
                acc[12] += xs_ * w3.x; acc[13] += xs_ * w3.y; acc[14] += xs_ * w3.z; acc[15] += xs_ * w3.w;
            }
        }
    }

    if (myNode < n) {
#pragma unroll
        for (int q = 0; q < 4; q++)
            g_hA16[myNode * 4 + q] = make_uint2(pack2(acc[q*4+0], acc[q*4+1]),
                                                pack2(acc[q*4+2], acc[q*4+3]));
    }
}

// ---------------- scale hA in place by dis (fork branch, after evDis) ----------------
__global__ void scale_hA(int n) {
    int i = blockIdx.x * 256 + threadIdx.x;
    if (i >= n * 4) return;
    float d = g_dis[i >> 2];
    uint2 v = g_hA16[i];
    float2 a = unpack2(v.x), b = unpack2(v.y);
    g_hA16[i] = make_uint2(pack2(a.x * d, a.y * d), pack2(b.x * d, b.y * d));
}

// ---------------- 16-wide fp16 gather (R14 body) ----------------
__global__ void gather16(int which, int n) {
    int w = (blockIdx.x * 256 + threadIdx.x) >> 5;
    if (w >= n) return;
    int lane = threadIdx.x & 31;
    int q = lane & 3, sub = lane >> 2;
    int start = g_rowstart[w], deg = g_rowstart[w + 1] - start;

    const uint2* __restrict__ h = (which == 0) ? g_hA16 : g_hB16;
    float4* __restrict__ agg    = (which == 0) ? g_aggA : g_aggB;

    float4 acc = make_float4(0.f, 0.f, 0.f, 0.f);
    for (int base = 0; base < deg; base += 32) {
        int p = base + lane;
        int idx = (p < deg) ? __ldg(&g_csr[start + p]) : 0;
        int s0 = __shfl_sync(0xffffffffu, idx, sub);
        int s1 = __shfl_sync(0xffffffffu, idx, sub + 8);
        int s2 = __shfl_sync(0xffffffffu, idx, sub + 16);
        int s3 = __shfl_sync(0xffffffffu, idx, sub + 24);
        uint2 z = make_uint2(0u, 0u);
        uint2 a = (base + sub)      < deg ? __ldg(&h[s0 * 4 + q]) : z;
        uint2 b = (base + sub + 8)  < deg ? __ldg(&h[s1 * 4 + q]) : z;
        uint2 c = (base + sub + 16) < deg ? __ldg(&h[s2 * 4 + q]) : z;
        uint2 d = (base + sub + 24) < deg ? __ldg(&h[s3 * 4 + q]) : z;
        float2 t;
        t = unpack2(a.x); acc.x += t.x; acc.y += t.y;
        t = unpack2(a.y); acc.z += t.x; acc.w += t.y;
        t = unpack2(b.x); acc.x += t.x; acc.y += t.y;
        t = unpack2(b.y); acc.z += t.x; acc.w += t.y;
        t = unpack2(c.x); acc.x += t.x; acc.y += t.y;
        t = unpack2(c.y); acc.z += t.x; acc.w += t.y;
        t = unpack2(d.x); acc.x += t.x; acc.y += t.y;
        t = unpack2(d.y); acc.z += t.x; acc.w += t.y;
    }
#pragma unroll
    for (int m = 4; m < 32; m <<= 1) {
        acc.x += __shfl_xor_sync(0xffffffffu, acc.x, m);
        acc.y += __shfl_xor_sync(0xffffffffu, acc.y, m);
        acc.z += __shfl_xor_sync(0xffffffffu, acc.z, m);
        acc.w += __shfl_xor_sync(0xffffffffu, acc.w, m);
    }
    if (sub == 0) {
        uint2 hv = __ldg(&h[w * 4 + q]);   // self-loop
        float2 t0 = unpack2(hv.x), t1 = unpack2(hv.y);
        float d = g_dis[w];
        agg[w * 4 + q] = make_float4((acc.x + t0.x) * d, (acc.y + t0.y) * d,
                                     (acc.z + t1.x) * d, (acc.w + t1.y) * d);
    }
}

// ---------------- layer 2 transform ----------------
__global__ void transform_mid(const float* __restrict__ bias, const float4* __restrict__ W, int n) {
    __shared__ float4 Ws[64];
    __shared__ float  bs[16];
    int tid = threadIdx.x;
    if (tid < 64) Ws[tid] = W[tid];
    if (tid < 16) bs[tid] = bias[tid];
    __syncthreads();
    int i = blockIdx.x * 256 + tid;
    if (i >= n) return;

    float z[16];
#pragma unroll
    for (int q = 0; q < 4; q++) {
        float4 v = g_aggA[i * 4 + q];
        z[q*4+0] = fmaxf(v.x + bs[q*4+0], 0.f);
        z[q*4+1] = fmaxf(v.y + bs[q*4+1], 0.f);
        z[q*4+2] = fmaxf(v.z + bs[q*4+2], 0.f);
        z[q*4+3] = fmaxf(v.w + bs[q*4+3], 0.f);
    }
    float4 o0 = make_float4(0.f,0.f,0.f,0.f), o1 = o0, o2 = o0, o3 = o0;
#pragma unroll
    for (int j = 0; j < 16; j++) {
        float zj = z[j];
        float4 w0 = Ws[j*4+0], w1 = Ws[j*4+1], w2 = Ws[j*4+2], w3 = Ws[j*4+3];
        o0.x += zj*w0.x; o0.y += zj*w0.y; o0.z += zj*w0.z; o0.w += zj*w0.w;
        o1.x += zj*w1.x; o1.y += zj*w1.y; o1.z += zj*w1.z; o1.w += zj*w1.w;
        o2.x += zj*w2.x; o2.y += zj*w2.y; o2.z += zj*w2.z; o2.w += zj*w2.w;
        o3.x += zj*w3.x; o3.y += zj*w3.y; o3.z += zj*w3.z; o3.w += zj*w3.w;
    }
    float d = g_dis[i];
    g_hB16[i*4+0] = make_uint2(pack2(o0.x*d, o0.y*d), pack2(o0.z*d, o0.w*d));
    g_hB16[i*4+1] = make_uint2(pack2(o1.x*d, o1.y*d), pack2(o1.z*d, o1.w*d));
    g_hB16[i*4+2] = make_uint2(pack2(o2.x*d, o2.y*d), pack2(o2.z*d, o2.w*d));
    g_hB16[i*4+3] = make_uint2(pack2(o3.x*d, o3.y*d), pack2(o3.z*d, o3.w*d));
}

// ---------------- layer 3 transform ----------------
__global__ void transform_last(const float* __restrict__ bias, const float* __restrict__ W3, int n) {
    __shared__ float Ws[32];
    __shared__ float bs[16];
    int tid = threadIdx.x;
    if (tid < 32) Ws[tid] = W3[tid];
    if (tid < 16) bs[tid] = bias[tid];
    __syncthreads();
    int i = blockIdx.x * 256 + tid;
    if (i >= n) return;

    float z[16];
#pragma unroll
    for (int q = 0; q < 4; q++) {
        float4 v = g_aggB[i * 4 + q];
        z[q*4+0] = fmaxf(v.x + bs[q*4+0], 0.f);
        z[q*4+1] = fmaxf(v.y + bs[q*4+1], 0.f);
        z[q*4+2] = fmaxf(v.z + bs[q*4+2], 0.f);
        z[q*4+3] = fmaxf(v.w + bs[q*4+3], 0.f);
    }
    float o0 = 0.f, o1 = 0.f;
#pragma unroll
    for (int j = 0; j < 16; j++) {
        o0 += z[j] * Ws[j*2+0];
        o1 += z[j] * Ws[j*2+1];
    }
    float d = g_dis[i];
    g_h3[i] = make_float2(o0 * d, o1 * d);
}

// ---------------- 2-wide gather fused with log_softmax ----------------
__global__ void gather2_out(const float* __restrict__ b3, float* __restrict__ out, int n) {
    int w = (blockIdx.x * 256 + threadIdx.x) >> 5;
    if (w >= n) return;
    int lane = threadIdx.x & 31;
    int start = g_rowstart[w], end = g_rowstart[w + 1];

    float2 acc = make_float2(0.f, 0.f);
    for (int p = start + lane; p < end; p += 32) {
        int src = __ldg(&g_csr[p]);
        float2 v = __ldg(&g_h3[src]);
        acc.x += v.x; acc.y += v.y;
    }
#pragma unroll
    for (int m = 1; m < 32; m <<= 1) {
        acc.x += __shfl_xor_sync(0xffffffffu, acc.x, m);
        acc.y += __shfl_xor_sync(0xffffffffu, acc.y, m);
    }
    if (lane == 0) {
        float2 hv = g_h3[w];
        float d = g_dis[w];
        float a0 = (acc.x + hv.x) * d + b3[0];
        float a1 = (acc.y + hv.y) * d + b3[1];
        float m0 = fmaxf(a0, a1);
        float lse = m0 + logf(expf(a0 - m0) + expf(a1 - m0));
        out[w * 2 + 0] = a0 - lse;
        out[w * 2 + 1] = a1 - lse;
    }
}

// ---------------- launch ----------------
extern "C" void kernel_launch(void* const* d_in, const int* in_sizes, int n_in,
                              void* d_out, int out_size) {
    const float* x  = (const float*)d_in[0];
    const int*   ei = (const int*)d_in[1];
    const float* W1 = (const float*)d_in[2];
    const float* b1 = (const float*)d_in[3];
    const float* W2 = (const float*)d_in[4];
    const float* b2 = (const float*)d_in[5];
    const float* W3 = (const float*)d_in[6];
    const float* b3 = (const float*)d_in[7];
    float* out = (float*)d_out;

    int n = in_sizes[0] / 128;   // 100000
    int e = in_sizes[1] / 2;     // 3200000

    int nb  = (n + 255) / 256;       // 391
    int ebk = (e + 255) / 256;       // 12500
    int wgb = (n * 32 + 255) / 256;
    int sb  = (n * 4 + 255) / 256;

    void* degp = nullptr;
    cudaGetSymbolAddress(&degp, g_deg);

    // ---- fork: gemm_in on s2, concurrent with CSR build ----
    cudaEventRecord(g_evFork, 0);
    cudaStreamWaitEvent(g_s2, g_evFork, 0);
    gemm_in<<<nb, 256, 0, g_s2>>>((const float4*)x, (const float4*)W1, n);

    // ---- CSR build chain on main stream ----
    cudaMemsetAsync(degp, 0, (size_t)n * sizeof(int));
    count_rank<<<ebk, 256>>>(ei, e);
    scanA<<<nb, 256>>>(n);
    scanB<<<nb, 256>>>(n);
    cudaEventRecord(g_evDis, 0);

    // ---- scale_hA on s2 (needs gemm result + dis); overlaps fill_pos ----
    cudaStreamWaitEvent(g_s2, g_evDis, 0);
    scale_hA<<<sb, 256, 0, g_s2>>>(n);
    cudaEventRecord(g_evJoin, g_s2);

    fill_pos<<<ebk, 256>>>(ei, e);

    // ---- join, then message passing ----
    cudaStreamWaitEvent(0, g_evJoin, 0);
    gather16<<<wgb, 256>>>(0, n);
    transform_mid<<<nb, 256>>>(b1, (const float4*)W2, n);

    gather16<<<wgb, 256>>>(1, n);
    transform_last<<<nb, 256>>>(b2, W3, n);

    gather2_out<<<wgb, 256>>>(b3, out, n);
}